// round 4
// baseline (speedup 1.0000x reference)
#include <cuda_runtime.h>
#include <math.h>

#define NMAX   100000
#define HIDDIM 128

// Scratch (device globals: no allocation inside kernel_launch allowed)
__device__ float g_deg[NMAX];
__device__ float g_dinv[NMAX];
__device__ float g_h  [(size_t)NMAX * HIDDIM];
__device__ float g_agg[(size_t)NMAX * HIDDIM];
__device__ float g_xbf[(size_t)NMAX * HIDDIM];
__device__ float g_pooled[HIDDIM];

// ---------------------------------------------------------------------------
// 1. degree init: deg[i] = 1 (self loop), pooled = 0
__global__ void k_init(int N)
{
    int i = blockIdx.x * blockDim.x + threadIdx.x;
    if (i < N) g_deg[i] = 1.0f;
    if (blockIdx.x == 0 && threadIdx.x < HIDDIM) g_pooled[threadIdx.x] = 0.0f;
}

// 2. degree count over targets (bounds-checked)
__global__ void k_degcount(const int* __restrict__ col, int E, int N)
{
    int e = blockIdx.x * blockDim.x + threadIdx.x;
    if (e < E) {
        unsigned c = (unsigned)col[e];
        if (c < (unsigned)N) atomicAdd(&g_deg[c], 1.0f);
    }
}

// 3. dinv = rsqrt(deg)   (deg >= 1 always)
__global__ void k_dinv(int N)
{
    int i = blockIdx.x * blockDim.x + threadIdx.x;
    if (i < N) g_dinv[i] = rsqrtf(g_deg[i]);
}

// ---------------------------------------------------------------------------
// 4. GEMM  H = X @ W  (N x 128 @ 128 x 128), fused self-loop epilogue:
//    AGG[n] = H[n] * dinv[n]^2
// IMPORTANT: X source is selected IN DEVICE CODE (use_global flag) — never
// pass a __device__ symbol address from host (on GB300/ATS that silently
// reads the host shadow = zeros instead of trapping).
__global__ __launch_bounds__(256) void k_gemm(const float* __restrict__ Xin,
                                              int use_global,
                                              const float* __restrict__ W,
                                              int N)
{
    __shared__ float Ws[64 * 128];   // 32 KB
    __shared__ float Xs[64 * 64];    // 16 KB   (total 48 KB)

    const float* __restrict__ X = use_global ? (const float*)g_xbf : Xin;

    const int t = threadIdx.x;
    const int c = t & 31;      // column group (4 cols)
    const int r = t >> 5;      // node group (8 nodes)
    const int node0 = blockIdx.x * 64;

    float acc[8][4];
#pragma unroll
    for (int i = 0; i < 8; i++)
#pragma unroll
        for (int j = 0; j < 4; j++) acc[i][j] = 0.0f;

    for (int k0 = 0; k0 < 128; k0 += 64) {
        {
            const float4* src = (const float4*)(W + (size_t)k0 * 128);
            float4* dst = (float4*)Ws;
            for (int q = t; q < 64 * 32; q += 256) dst[q] = src[q];
        }
        {
            for (int q = t; q < 64 * 16; q += 256) {
                int n = q >> 4, kq = q & 15;
                int gn = node0 + n;
                float4 v = make_float4(0.f, 0.f, 0.f, 0.f);
                if (gn < N)
                    v = *(const float4*)(X + (size_t)gn * 128 + k0 + kq * 4);
                *(float4*)&Xs[n * 64 + kq * 4] = v;
            }
        }
        __syncthreads();

#pragma unroll 8
        for (int kk = 0; kk < 64; kk++) {
            float4 wv = *(const float4*)&Ws[kk * 128 + c * 4];
#pragma unroll
            for (int i = 0; i < 8; i++) {
                float xv = Xs[(r * 8 + i) * 64 + kk];   // warp-broadcast LDS
                acc[i][0] += xv * wv.x;
                acc[i][1] += xv * wv.y;
                acc[i][2] += xv * wv.z;
                acc[i][3] += xv * wv.w;
            }
        }
        __syncthreads();
    }

#pragma unroll
    for (int i = 0; i < 8; i++) {
        int gn = node0 + r * 8 + i;
        if (gn < N) {
            float d = g_dinv[gn];
            float d2 = d * d;
            float4 v = make_float4(acc[i][0], acc[i][1], acc[i][2], acc[i][3]);
            *(float4*)(g_h + (size_t)gn * 128 + c * 4) = v;
            float4 a = make_float4(v.x * d2, v.y * d2, v.z * d2, v.w * d2);
            *(float4*)(g_agg + (size_t)gn * 128 + c * 4) = a;
        }
    }
}

// ---------------------------------------------------------------------------
// 5. edge scatter: AGG[col] += H[row] * dinv[row]*dinv[col]
// One warp per edge, each lane handles one float4 (16 B) of the 512 B row.
__global__ void k_scatter(const int* __restrict__ row,
                          const int* __restrict__ col, int E, int N)
{
    int warp = (blockIdx.x * blockDim.x + threadIdx.x) >> 5;
    int lane = threadIdx.x & 31;
    if (warp >= E) return;
    unsigned rs = (unsigned)row[warp];
    unsigned cd = (unsigned)col[warp];
    if (rs >= (unsigned)N || cd >= (unsigned)N) return;   // defensive
    float coef = g_dinv[rs] * g_dinv[cd];
    float4 v = ((const float4*)(g_h + (size_t)rs * 128))[lane];
    v.x *= coef; v.y *= coef; v.z *= coef; v.w *= coef;
    float4* dst = (float4*)(g_agg + (size_t)cd * 128) + lane;
    atomicAdd(dst, v);    // sm_90+ 16B vector red
}

// ---------------------------------------------------------------------------
// 6. ELU(agg + b) -> g_xbf
__global__ void k_elu(const float* __restrict__ b, int total)
{
    int i = blockIdx.x * blockDim.x + threadIdx.x;
    if (i < total) {
        float v = g_agg[i] + b[i & 127];
        g_xbf[i] = v > 0.0f ? v : expm1f(v);
    }
}

// ---------------------------------------------------------------------------
// 7. column sums of final activations -> g_pooled
__global__ void k_pool(int N)
{
    int j = threadIdx.x;   // 128 threads
    float s = 0.0f;
    for (int n = blockIdx.x; n < N; n += gridDim.x)
        s += g_xbf[(size_t)n * 128 + j];
    atomicAdd(&g_pooled[j], s);
}

// 8. out[j] = (pooled/N) @ lin_w + lin_b
__global__ void k_final(const float* __restrict__ lin_w,
                        const float* __restrict__ lin_b,
                        float* __restrict__ out, int N)
{
    int j = threadIdx.x;
    if (j < 24) {
        float invn = 1.0f / (float)N;
        float s = lin_b[j];
#pragma unroll 8
        for (int k = 0; k < 128; k++)
            s += g_pooled[k] * invn * lin_w[k * 24 + j];
        out[j] = s;
    }
}

// ---------------------------------------------------------------------------
extern "C" void kernel_launch(void* const* d_in, const int* in_sizes, int n_in,
                              void* d_out, int out_size)
{
    // ---- Input identification: exact sizes (unit-agnostic), ignore extras.
    // Element counts: x=12800000, edge=1200000, W=16384(x3), lin_w=3072,
    //                 b=128(x3), lin_b=24.
    int unit = 1;                           // 1 = sizes in elements
    {
        bool has24 = false, has96 = false;
        for (int i = 0; i < n_in; i++) {
            if (in_sizes[i] == 24) has24 = true;
            if (in_sizes[i] == 96) has96 = true;
        }
        if (!has24 && has96) unit = 4;      // sizes appear to be bytes
    }

    const float* x = nullptr;  const int* eidx = nullptr;
    const float* Ws[3] = {nullptr,nullptr,nullptr};
    const float* bs[3] = {nullptr,nullptr,nullptr};
    const float* lin_w = nullptr; const float* lin_b = nullptr;
    int iW = 0, ib = 0;

    for (int i = 0; i < n_in; i++) {
        long s = (long)in_sizes[i] / unit;
        if      (s == 12800000 && !x)      x     = (const float*)d_in[i];
        else if (s == 1200000  && !eidx)   eidx  = (const int*)  d_in[i];
        else if (s == 16384 && iW < 3)     Ws[iW++] = (const float*)d_in[i];
        else if (s == 3072  && !lin_w)     lin_w = (const float*)d_in[i];
        else if (s == 128   && ib < 3)     bs[ib++] = (const float*)d_in[i];
        else if (s == 24    && !lin_b)     lin_b = (const float*)d_in[i];
    }

    // Fallback: rank-based mapping if exact-size matching missed anything.
    if (!x || !eidx || iW < 3 || ib < 3 || !lin_w || !lin_b) {
        int order[32];
        int m = (n_in < 32) ? n_in : 32;
        for (int i = 0; i < m; i++) order[i] = i;
        for (int i = 0; i < m; i++) {       // stable selection sort desc
            int best = i;
            for (int j = i + 1; j < m; j++)
                if (in_sizes[order[j]] > in_sizes[order[best]]) best = j;
            int tmp = order[best];
            for (int j = best; j > i; j--) order[j] = order[j - 1];
            order[i] = tmp;
        }
        if (m < 10) return;
        x     = (const float*)d_in[order[0]];
        eidx  = (const int*)  d_in[order[1]];
        Ws[0] = (const float*)d_in[order[2]];
        Ws[1] = (const float*)d_in[order[3]];
        Ws[2] = (const float*)d_in[order[4]];
        lin_w = (const float*)d_in[order[5]];
        bs[0] = (const float*)d_in[order[6]];
        bs[1] = (const float*)d_in[order[7]];
        bs[2] = (const float*)d_in[order[8]];
        lin_b = (const float*)d_in[order[9]];
    }
    float* out = (float*)d_out;

    const int N = 100000;
    const int E = 600000;
    const int* e_row = eidx;                  // sources
    const int* e_col = eidx + E;              // targets
    const int total = N * HIDDIM;

    // degree / norm
    k_init<<<(N + 255) / 256, 256>>>(N);
    k_degcount<<<(E + 255) / 256, 256>>>(e_col, E, N);
    k_dinv<<<(N + 255) / 256, 256>>>(N);

    const int gemm_blocks = (N + 63) / 64;
    const int scat_blocks = (E + 7) / 8;      // 8 warps (edges) per 256-thread block
    const int elu_blocks  = (total + 255) / 256;

    for (int l = 0; l < 3; l++) {
        // Layer 0 reads harness input x; layers 1-2 read g_xbf selected
        // inside the kernel (use_global=1). Host never forms a device-symbol
        // pointer.
        k_gemm<<<gemm_blocks, 256>>>(x, l > 0 ? 1 : 0, Ws[l], N);
        k_scatter<<<scat_blocks, 256>>>(e_row, e_col, E, N);
        k_elu<<<elu_blocks, 256>>>(bs[l], total);
    }

    k_pool<<<512, 128>>>(N);
    k_final<<<1, 32>>>(lin_w, lin_b, out, N);
}

// round 5
// speedup vs baseline: 1.2741x; 1.2741x over previous
#include <cuda_runtime.h>
#include <math.h>

#define NMAX   100000
#define EMAX   600000
#define HIDDIM 128

// Scratch (device globals: no allocation inside kernel_launch allowed)
__device__ float g_deg[NMAX];
__device__ float g_dinv[NMAX];
__device__ int   g_head[NMAX];
__device__ int   g_next[EMAX];
__device__ float g_h  [(size_t)NMAX * HIDDIM];
__device__ float g_agg[(size_t)NMAX * HIDDIM];
__device__ float g_pooled[HIDDIM];

__device__ __forceinline__ float elu1(float x) { return x > 0.0f ? x : expm1f(x); }

// ---------------------------------------------------------------------------
// 1. init: deg=1 (self loop), head=-1, pooled=0
__global__ void k_init(int N)
{
    int i = blockIdx.x * blockDim.x + threadIdx.x;
    if (i < N) { g_deg[i] = 1.0f; g_head[i] = -1; }
    if (blockIdx.x == 0 && threadIdx.x < HIDDIM) g_pooled[threadIdx.x] = 0.0f;
}

// 2. build per-target linked lists + degree count
__global__ void k_lbuild(const int* __restrict__ col, int E, int N)
{
    int e = blockIdx.x * blockDim.x + threadIdx.x;
    if (e < E) {
        unsigned c = (unsigned)col[e];
        if (c < (unsigned)N) {
            g_next[e] = atomicExch(&g_head[c], e);
            atomicAdd(&g_deg[c], 1.0f);
        }
    }
}

// 3. dinv = rsqrt(deg)
__global__ void k_dinv(int N)
{
    int i = blockIdx.x * blockDim.x + threadIdx.x;
    if (i < N) g_dinv[i] = rsqrtf(g_deg[i]);
}

// ---------------------------------------------------------------------------
// 4. GEMM  H = ACT(Xsrc) @ W   (N x 128 @ 128 x 128)  ->  g_h only
//    layer 0: ACT = identity on harness input Xin
//    layer>0: ACT = elu(g_agg + b_prev)  (fused, device-side source select —
//             never form a __device__ symbol pointer on host: GB300 ATS
//             silently reads the host shadow as zeros)
__global__ __launch_bounds__(256) void k_gemm(const float* __restrict__ Xin,
                                              int layer,
                                              const float* __restrict__ bprev,
                                              const float* __restrict__ W,
                                              int N)
{
    __shared__ float Ws[64 * 128];   // 32 KB
    __shared__ float Xs[64 * 64];    // 16 KB

    const int t = threadIdx.x;
    const int c = t & 31;      // column group (4 cols)
    const int r = t >> 5;      // node group (8 nodes)
    const int node0 = blockIdx.x * 64;

    float acc[8][4];
#pragma unroll
    for (int i = 0; i < 8; i++)
#pragma unroll
        for (int j = 0; j < 4; j++) acc[i][j] = 0.0f;

    for (int k0 = 0; k0 < 128; k0 += 64) {
        // stage W chunk (64 rows x 128 cols)
        {
            const float4* src = (const float4*)(W + (size_t)k0 * 128);
            float4* dst = (float4*)Ws;
            for (int q = t; q < 64 * 32; q += 256) dst[q] = src[q];
        }
        // stage X tile (64 nodes x 64 k) with fused bias+ELU for layer>0
        {
            for (int q = t; q < 64 * 16; q += 256) {
                int n = q >> 4, kq = q & 15;
                int gn = node0 + n;
                float4 v = make_float4(0.f, 0.f, 0.f, 0.f);
                if (gn < N) {
                    if (layer == 0) {
                        v = *(const float4*)(Xin + (size_t)gn * 128 + k0 + kq * 4);
                    } else {
                        float4 a = *(const float4*)(g_agg + (size_t)gn * 128 + k0 + kq * 4);
                        float4 bb = *(const float4*)(bprev + k0 + kq * 4);
                        v.x = elu1(a.x + bb.x);
                        v.y = elu1(a.y + bb.y);
                        v.z = elu1(a.z + bb.z);
                        v.w = elu1(a.w + bb.w);
                    }
                }
                *(float4*)&Xs[n * 64 + kq * 4] = v;
            }
        }
        __syncthreads();

#pragma unroll
        for (int kk = 0; kk < 64; kk += 4) {
            float4 w0 = *(const float4*)&Ws[(kk + 0) * 128 + c * 4];
            float4 w1 = *(const float4*)&Ws[(kk + 1) * 128 + c * 4];
            float4 w2 = *(const float4*)&Ws[(kk + 2) * 128 + c * 4];
            float4 w3 = *(const float4*)&Ws[(kk + 3) * 128 + c * 4];
#pragma unroll
            for (int i = 0; i < 8; i++) {
                float4 xv = *(const float4*)&Xs[(r * 8 + i) * 64 + kk];  // broadcast
                acc[i][0] = fmaf(xv.x, w0.x, fmaf(xv.y, w1.x, fmaf(xv.z, w2.x, fmaf(xv.w, w3.x, acc[i][0]))));
                acc[i][1] = fmaf(xv.x, w0.y, fmaf(xv.y, w1.y, fmaf(xv.z, w2.y, fmaf(xv.w, w3.y, acc[i][1]))));
                acc[i][2] = fmaf(xv.x, w0.z, fmaf(xv.y, w1.z, fmaf(xv.z, w2.z, fmaf(xv.w, w3.z, acc[i][2]))));
                acc[i][3] = fmaf(xv.x, w0.w, fmaf(xv.y, w1.w, fmaf(xv.z, w2.w, fmaf(xv.w, w3.w, acc[i][3]))));
            }
        }
        __syncthreads();
    }

#pragma unroll
    for (int i = 0; i < 8; i++) {
        int gn = node0 + r * 8 + i;
        if (gn < N) {
            float4 v = make_float4(acc[i][0], acc[i][1], acc[i][2], acc[i][3]);
            *(float4*)(g_h + (size_t)gn * 128 + c * 4) = v;
        }
    }
}

// ---------------------------------------------------------------------------
// 5. gather aggregation (no atomics): one warp per node v
//    agg[v] = h[v]*dinv[v]^2 + sum_{e: col[e]==v} h[row[e]] * dinv[row]*dinv[v]
__global__ void k_gather(const int* __restrict__ row, int N)
{
    int v = (blockIdx.x * blockDim.x + threadIdx.x) >> 5;
    int lane = threadIdx.x & 31;
    if (v >= N) return;

    float dv = g_dinv[v];
    float4 acc = ((const float4*)(g_h + (size_t)v * 128))[lane];
    float d2 = dv * dv;
    acc.x *= d2; acc.y *= d2; acc.z *= d2; acc.w *= d2;

    int e = g_head[v];                       // uniform across warp
    while (e >= 0) {
        unsigned u = (unsigned)row[e];
        if (u < (unsigned)N) {
            float coef = g_dinv[u] * dv;
            float4 hv = ((const float4*)(g_h + (size_t)u * 128))[lane];
            acc.x = fmaf(hv.x, coef, acc.x);
            acc.y = fmaf(hv.y, coef, acc.y);
            acc.z = fmaf(hv.z, coef, acc.z);
            acc.w = fmaf(hv.w, coef, acc.w);
        }
        e = g_next[e];
    }
    ((float4*)(g_agg + (size_t)v * 128))[lane] = acc;
}

// ---------------------------------------------------------------------------
// 6. pooled column sums of elu(agg + b2)
__global__ void k_pool(const float* __restrict__ b2, int N)
{
    int j = threadIdx.x;   // 128 threads
    float bj = b2[j];
    float s = 0.0f;
    for (int n = blockIdx.x; n < N; n += gridDim.x)
        s += elu1(g_agg[(size_t)n * 128 + j] + bj);
    atomicAdd(&g_pooled[j], s);
}

// 7. out[j] = (pooled/N) @ lin_w + lin_b
__global__ void k_final(const float* __restrict__ lin_w,
                        const float* __restrict__ lin_b,
                        float* __restrict__ out, int N)
{
    int j = threadIdx.x;
    if (j < 24) {
        float invn = 1.0f / (float)N;
        float s = lin_b[j];
#pragma unroll 8
        for (int k = 0; k < 128; k++)
            s += g_pooled[k] * invn * lin_w[k * 24 + j];
        out[j] = s;
    }
}

// ---------------------------------------------------------------------------
extern "C" void kernel_launch(void* const* d_in, const int* in_sizes, int n_in,
                              void* d_out, int out_size)
{
    // ---- Input identification: exact sizes (unit-agnostic), ignore extras.
    int unit = 1;
    {
        bool has24 = false, has96 = false;
        for (int i = 0; i < n_in; i++) {
            if (in_sizes[i] == 24) has24 = true;
            if (in_sizes[i] == 96) has96 = true;
        }
        if (!has24 && has96) unit = 4;
    }

    const float* x = nullptr;  const int* eidx = nullptr;
    const float* Ws[3] = {nullptr,nullptr,nullptr};
    const float* bs[3] = {nullptr,nullptr,nullptr};
    const float* lin_w = nullptr; const float* lin_b = nullptr;
    int iW = 0, ib = 0;

    for (int i = 0; i < n_in; i++) {
        long s = (long)in_sizes[i] / unit;
        if      (s == 12800000 && !x)      x     = (const float*)d_in[i];
        else if (s == 1200000  && !eidx)   eidx  = (const int*)  d_in[i];
        else if (s == 16384 && iW < 3)     Ws[iW++] = (const float*)d_in[i];
        else if (s == 3072  && !lin_w)     lin_w = (const float*)d_in[i];
        else if (s == 128   && ib < 3)     bs[ib++] = (const float*)d_in[i];
        else if (s == 24    && !lin_b)     lin_b = (const float*)d_in[i];
    }
    if (!x || !eidx || iW < 3 || ib < 3 || !lin_w || !lin_b) {
        int order[32];
        int m = (n_in < 32) ? n_in : 32;
        for (int i = 0; i < m; i++) order[i] = i;
        for (int i = 0; i < m; i++) {
            int best = i;
            for (int j = i + 1; j < m; j++)
                if (in_sizes[order[j]] > in_sizes[order[best]]) best = j;
            int tmp = order[best];
            for (int j = best; j > i; j--) order[j] = order[j - 1];
            order[i] = tmp;
        }
        if (m < 10) return;
        x     = (const float*)d_in[order[0]];
        eidx  = (const int*)  d_in[order[1]];
        Ws[0] = (const float*)d_in[order[2]];
        Ws[1] = (const float*)d_in[order[3]];
        Ws[2] = (const float*)d_in[order[4]];
        lin_w = (const float*)d_in[order[5]];
        bs[0] = (const float*)d_in[order[6]];
        bs[1] = (const float*)d_in[order[7]];
        bs[2] = (const float*)d_in[order[8]];
        lin_b = (const float*)d_in[order[9]];
    }
    float* out = (float*)d_out;

    const int N = 100000;
    const int E = 600000;
    const int* e_row = eidx;                  // sources
    const int* e_col = eidx + E;              // targets

    // graph structure (rebuilt every call — deterministic work)
    k_init<<<(N + 255) / 256, 256>>>(N);
    k_lbuild<<<(E + 255) / 256, 256>>>(e_col, E, N);
    k_dinv<<<(N + 255) / 256, 256>>>(N);

    const int gemm_blocks   = (N + 63) / 64;
    const int gather_blocks = (N + 7) / 8;    // 8 warps (nodes) per 256-thread block

    for (int l = 0; l < 3; l++) {
        k_gemm<<<gemm_blocks, 256>>>(x, l, l > 0 ? bs[l - 1] : nullptr, Ws[l], N);
        k_gather<<<gather_blocks, 256>>>(e_row, N);
    }

    k_pool<<<512, 128>>>(bs[2], N);
    k_final<<<1, 32>>>(lin_w, lin_b, out, N);
}